// round 7
// baseline (speedup 1.0000x reference)
#include <cuda_runtime.h>
#include <cuda_bf16.h>
#include <cstdint>

// out[b,t,o] = (cummean_t x)[b,t,:] . W[t,:,o]
// B=4, T=1024, D=256, O=256. All fp32.

#define BB 4
#define TT 1024
#define DD 256
#define OO 256

#define NSEG 64
#define SEGLEN 16     // NSEG*SEGLEN == TT
#define QLEN 4        // quarter length; 4 quarters per segment

#define STAGES 4
#define DCHUNK 4                 // d-rows per stage
#define NCHUNK (DD / DCHUNK)     // 64

__device__ float g_segsum[BB * NSEG * DD];      // 256 KB (L2-resident)
__device__ float g_cm[BB * TT * DD];            // 4 MB cumulative mean

// ---------------------------------------------------------------------------
// Kernel 1: per-segment sums. grid = B*NSEG = 256 blocks, 256 threads.
// ---------------------------------------------------------------------------
__global__ __launch_bounds__(256) void k_segsum(const float* __restrict__ x) {
    __shared__ float4 qs[4][64];

    int b = blockIdx.x / NSEG;
    int s = blockIdx.x % NSEG;
    int d4 = threadIdx.x & 63;
    int q  = threadIdx.x >> 6;

    const float4* xp = reinterpret_cast<const float4*>(x) +
                       (size_t)(b * TT + s * SEGLEN + q * QLEN) * (DD / 4) + d4;
    float4 sum = make_float4(0.f, 0.f, 0.f, 0.f);
#pragma unroll
    for (int i = 0; i < QLEN; ++i) {
        float4 v = xp[(size_t)i * (DD / 4)];
        sum.x += v.x; sum.y += v.y; sum.z += v.z; sum.w += v.w;
    }
    qs[q][d4] = sum;
    __syncthreads();

    if (q == 0) {
        float4 a = qs[0][d4], b1 = qs[1][d4], c = qs[2][d4], d = qs[3][d4];
        float4 r;
        r.x = (a.x + b1.x) + (c.x + d.x);
        r.y = (a.y + b1.y) + (c.y + d.y);
        r.z = (a.z + b1.z) + (c.z + d.z);
        r.w = (a.w + b1.w) + (c.w + d.w);
        reinterpret_cast<float4*>(g_segsum)[(size_t)(b * NSEG + s) * (DD / 4) + d4] = r;
    }
}

// ---------------------------------------------------------------------------
// Kernel 2: cumulative mean. grid = B*NSEG = 256 blocks, 256 threads.
// ---------------------------------------------------------------------------
__global__ __launch_bounds__(256) void k_cummean(const float* __restrict__ x) {
    __shared__ float4 qs[4][64];

    int b = blockIdx.x / NSEG;
    int s = blockIdx.x % NSEG;
    int d4 = threadIdx.x & 63;
    int q  = threadIdx.x >> 6;

    int tbase = s * SEGLEN + q * QLEN;
    const float4* xp = reinterpret_cast<const float4*>(x) +
                       (size_t)(b * TT + tbase) * (DD / 4) + d4;

    float4 v0 = xp[0 * (DD / 4)];
    float4 v1 = xp[1 * (DD / 4)];
    float4 v2 = xp[2 * (DD / 4)];
    float4 v3 = xp[3 * (DD / 4)];

    float4 qsum;
    qsum.x = (v0.x + v1.x) + (v2.x + v3.x);
    qsum.y = (v0.y + v1.y) + (v2.y + v3.y);
    qsum.z = (v0.z + v1.z) + (v2.z + v3.z);
    qsum.w = (v0.w + v1.w) + (v2.w + v3.w);
    qs[q][d4] = qsum;

    const float4* ss = reinterpret_cast<const float4*>(g_segsum) +
                       (size_t)b * NSEG * (DD / 4) + d4;
    float4 r0 = make_float4(0.f, 0.f, 0.f, 0.f);
    float4 r1 = r0, r2 = r0, r3 = r0;
    int sp = 0;
    for (; sp + 4 <= s; sp += 4) {
        float4 a = ss[(size_t)(sp + 0) * (DD / 4)];
        float4 bb = ss[(size_t)(sp + 1) * (DD / 4)];
        float4 c = ss[(size_t)(sp + 2) * (DD / 4)];
        float4 d = ss[(size_t)(sp + 3) * (DD / 4)];
        r0.x += a.x;  r0.y += a.y;  r0.z += a.z;  r0.w += a.w;
        r1.x += bb.x; r1.y += bb.y; r1.z += bb.z; r1.w += bb.w;
        r2.x += c.x;  r2.y += c.y;  r2.z += c.z;  r2.w += c.w;
        r3.x += d.x;  r3.y += d.y;  r3.z += d.z;  r3.w += d.w;
    }
    for (; sp < s; ++sp) {
        float4 a = ss[(size_t)sp * (DD / 4)];
        r0.x += a.x; r0.y += a.y; r0.z += a.z; r0.w += a.w;
    }
    float4 run;
    run.x = (r0.x + r1.x) + (r2.x + r3.x);
    run.y = (r0.y + r1.y) + (r2.y + r3.y);
    run.z = (r0.z + r1.z) + (r2.z + r3.z);
    run.w = (r0.w + r1.w) + (r2.w + r3.w);

    __syncthreads();
#pragma unroll
    for (int qp = 0; qp < 3; ++qp) {
        if (qp < q) {
            float4 a = qs[qp][d4];
            run.x += a.x; run.y += a.y; run.z += a.z; run.w += a.w;
        }
    }

    float4* cp = reinterpret_cast<float4*>(g_cm) +
                 (size_t)(b * TT + tbase) * (DD / 4) + d4;
#pragma unroll
    for (int i = 0; i < QLEN; ++i) {
        float4 v = (i == 0) ? v0 : (i == 1) ? v1 : (i == 2) ? v2 : v3;
        run.x += v.x; run.y += v.y; run.z += v.z; run.w += v.w;
        float inv = 1.0f / (float)(tbase + i + 1);
        float4 o;
        o.x = run.x * inv; o.y = run.y * inv; o.z = run.z * inv; o.w = run.w * inv;
        cp[(size_t)i * (DD / 4)] = o;
    }
}

// ---------------------------------------------------------------------------
// Kernel 3: GEMM, barrier-free cp.async pipeline.
// Thread (tg,o4) issues cp.asyncs for exactly the smem slots it later reads
// (ws[st][tg][0..3][o4]) -> per-thread wait_group is sufficient; no BARs in
// the mainloop. grid = T/2 = 512 blocks, 128 threads.
// ---------------------------------------------------------------------------
__device__ __forceinline__ void fma4(float4& acc, float s, const float4& v) {
    acc.x = fmaf(s, v.x, acc.x);
    acc.y = fmaf(s, v.y, acc.y);
    acc.z = fmaf(s, v.z, acc.z);
    acc.w = fmaf(s, v.w, acc.w);
}

__device__ __forceinline__ void cp16(void* smem_dst, const void* gmem_src) {
    uint32_t s = (uint32_t)__cvta_generic_to_shared(smem_dst);
    asm volatile("cp.async.cg.shared.global [%0], [%1], 16;\n"
                 :: "r"(s), "l"(gmem_src));
}

__global__ __launch_bounds__(128) void k_gemm(const float* __restrict__ W,
                                              float* __restrict__ out) {
    __shared__ float4 ws[STAGES][2][DCHUNK][OO / 4];  // 32 KB
    __shared__ float4 cm_s[2][BB][DD / 4];            // 8 KB

    int tid = threadIdx.x;
    int t0 = blockIdx.x * 2;
    int tg = tid >> 6;        // 0..1
    int o4 = tid & 63;        // float4 O-column

    const float4* W4 = reinterpret_cast<const float4*>(W);
    // base pointer for this thread's own W column (t = t0+tg, column o4)
    const float4* Wme = W4 + (size_t)(t0 + tg) * DD * (OO / 4) + o4;

    // per-thread issue: this thread's 4 slots of one chunk
    auto issue = [&](int st, int ch) {
#pragma unroll
        for (int dd = 0; dd < DCHUNK; ++dd) {
            cp16(&ws[st][tg][dd][o4],
                 Wme + (size_t)(ch * DCHUNK + dd) * (OO / 4));
        }
    };

#pragma unroll
    for (int p = 0; p < STAGES - 1; ++p) {
        issue(p, p);
        asm volatile("cp.async.commit_group;\n" ::: "memory");
    }

    // cooperative cm load (only cross-thread smem dependency -> one barrier)
    const float4* cm_g = reinterpret_cast<const float4*>(g_cm);
#pragma unroll
    for (int k = 0; k < 4; ++k) {
        int idx = tid + k * 128;
        int tg_ = idx >> 8;
        int b   = (idx >> 6) & 3;
        int d4_ = idx & 63;
        cm_s[tg_][b][d4_] = cm_g[(size_t)(b * TT + t0 + tg_) * (DD / 4) + d4_];
    }
    __syncthreads();

    float4 a0 = make_float4(0.f, 0.f, 0.f, 0.f);
    float4 a1 = a0, a2 = a0, a3 = a0;

    for (int ch = 0; ch < NCHUNK; ++ch) {
        asm volatile("cp.async.wait_group %0;\n" :: "n"(STAGES - 2) : "memory");

        int st = ch & (STAGES - 1);

        float4 c0 = cm_s[tg][0][ch];
        float4 c1 = cm_s[tg][1][ch];
        float4 c2 = cm_s[tg][2][ch];
        float4 c3 = cm_s[tg][3][ch];

        {
            float4 w = ws[st][tg][0][o4];
            fma4(a0, c0.x, w); fma4(a1, c1.x, w); fma4(a2, c2.x, w); fma4(a3, c3.x, w);
        }
        {
            float4 w = ws[st][tg][1][o4];
            fma4(a0, c0.y, w); fma4(a1, c1.y, w); fma4(a2, c2.y, w); fma4(a3, c3.y, w);
        }
        {
            float4 w = ws[st][tg][2][o4];
            fma4(a0, c0.z, w); fma4(a1, c1.z, w); fma4(a2, c2.z, w); fma4(a3, c3.z, w);
        }
        {
            float4 w = ws[st][tg][3][o4];
            fma4(a0, c0.w, w); fma4(a1, c1.w, w); fma4(a2, c2.w, w); fma4(a3, c3.w, w);
        }

        // this thread finished reading stage st of chunk ch; its own next
        // issue may overwrite stage (ch+STAGES-1)&3 == st-1 (already consumed
        // by this thread one chunk ago). purely thread-local: no barrier.
        int nxt = ch + STAGES - 1;
        if (nxt < NCHUNK)
            issue(nxt & (STAGES - 1), nxt);
        asm volatile("cp.async.commit_group;\n" ::: "memory");
    }

    int t = t0 + tg;
    float4* op = reinterpret_cast<float4*>(out);
    op[(size_t)(0 * TT + t) * (OO / 4) + o4] = a0;
    op[(size_t)(1 * TT + t) * (OO / 4) + o4] = a1;
    op[(size_t)(2 * TT + t) * (OO / 4) + o4] = a2;
    op[(size_t)(3 * TT + t) * (OO / 4) + o4] = a3;
}

extern "C" void kernel_launch(void* const* d_in, const int* in_sizes, int n_in,
                              void* d_out, int out_size) {
    const float* x = (const float*)d_in[0];   // (B,T,D)
    const float* W = (const float*)d_in[1];   // (T,D,O)
    float* out = (float*)d_out;               // (B,T,O)

    k_segsum<<<BB * NSEG, 256>>>(x);
    k_cummean<<<BB * NSEG, 256>>>(x);
    k_gemm<<<TT / 2, 128>>>(W, out);
}

// round 8
// speedup vs baseline: 1.0400x; 1.0400x over previous
#include <cuda_runtime.h>
#include <cuda_bf16.h>
#include <cstdint>

// out[b,t,o] = (cummean_t x)[b,t,:] . W[t,:,o]
// B=4, T=1024, D=256, O=256. All fp32.

#define BB 4
#define TT 1024
#define DD 256
#define OO 256

#define NSEG 64
#define SEGLEN 16     // NSEG*SEGLEN == TT
#define QLEN 4        // 4 quarters x 4 rows per segment

#define STAGES 5
#define DCHUNK 4                 // d-rows per stage
#define NCHUNK (DD / DCHUNK)     // 64

__device__ float g_segsum[BB * NSEG * DD];      // 256 KB (L2-resident)
__device__ float g_cm[BB * TT * DD];            // 4 MB cumulative mean
__device__ unsigned g_ready[BB * NSEG];         // publish flags

// ---------------------------------------------------------------------------
// Kernel 0: reset publish flags (graph-replay safe).
// ---------------------------------------------------------------------------
__global__ void k_reset() {
    g_ready[threadIdx.x] = 0u;
}

// ---------------------------------------------------------------------------
// Kernel 1: fused scan. grid = B*NSEG = 256 blocks (all co-resident),
// 256 threads = (q = tid>>6) x (d4 = tid&63).
// Phase 1: segment sum -> g_segsum, publish flag.
// Phase 2: poll prior segments' flags, prefix, write cumulative mean.
// x is read exactly once (rows kept in registers).
// ---------------------------------------------------------------------------
__device__ __forceinline__ unsigned ld_acquire(const unsigned* p) {
    unsigned v;
    asm volatile("ld.acquire.gpu.u32 %0, [%1];" : "=r"(v) : "l"(p));
    return v;
}

__global__ __launch_bounds__(256) void k_scan(const float* __restrict__ x) {
    __shared__ float4 qs[4][64];

    int b = blockIdx.x / NSEG;
    int s = blockIdx.x % NSEG;
    int d4 = threadIdx.x & 63;
    int q  = threadIdx.x >> 6;

    int tbase = s * SEGLEN + q * QLEN;
    const float4* xp = reinterpret_cast<const float4*>(x) +
                       (size_t)(b * TT + tbase) * (DD / 4) + d4;

    float4 v0 = xp[0 * (DD / 4)];
    float4 v1 = xp[1 * (DD / 4)];
    float4 v2 = xp[2 * (DD / 4)];
    float4 v3 = xp[3 * (DD / 4)];

    float4 qsum;
    qsum.x = (v0.x + v1.x) + (v2.x + v3.x);
    qsum.y = (v0.y + v1.y) + (v2.y + v3.y);
    qsum.z = (v0.z + v1.z) + (v2.z + v3.z);
    qsum.w = (v0.w + v1.w) + (v2.w + v3.w);
    qs[q][d4] = qsum;
    __syncthreads();

    // phase 1: q==0 threads write the segment sum, fence, then publish
    if (q == 0) {
        float4 a = qs[0][d4], b1 = qs[1][d4], c = qs[2][d4], d = qs[3][d4];
        float4 r;
        r.x = (a.x + b1.x) + (c.x + d.x);
        r.y = (a.y + b1.y) + (c.y + d.y);
        r.z = (a.z + b1.z) + (c.z + d.z);
        r.w = (a.w + b1.w) + (c.w + d.w);
        reinterpret_cast<float4*>(g_segsum)[(size_t)(b * NSEG + s) * (DD / 4) + d4] = r;
        __threadfence();
    }
    __syncthreads();
    if (threadIdx.x == 0)
        atomicExch(&g_ready[b * NSEG + s], 1u);

    // phase 2: wait for all prior segments of this b (parallel polling)
    if ((int)threadIdx.x < s) {
        const unsigned* flag = &g_ready[b * NSEG + threadIdx.x];
        while (ld_acquire(flag) == 0u) { }
    }
    __syncthreads();

    // prefix over prior segment sums (L2-resident, ILP-4)
    const float4* ss = reinterpret_cast<const float4*>(g_segsum) +
                       (size_t)b * NSEG * (DD / 4) + d4;
    float4 r0 = make_float4(0.f, 0.f, 0.f, 0.f);
    float4 r1 = r0, r2 = r0, r3 = r0;
    int sp = 0;
    for (; sp + 4 <= s; sp += 4) {
        float4 a = ss[(size_t)(sp + 0) * (DD / 4)];
        float4 bb = ss[(size_t)(sp + 1) * (DD / 4)];
        float4 c = ss[(size_t)(sp + 2) * (DD / 4)];
        float4 d = ss[(size_t)(sp + 3) * (DD / 4)];
        r0.x += a.x;  r0.y += a.y;  r0.z += a.z;  r0.w += a.w;
        r1.x += bb.x; r1.y += bb.y; r1.z += bb.z; r1.w += bb.w;
        r2.x += c.x;  r2.y += c.y;  r2.z += c.z;  r2.w += c.w;
        r3.x += d.x;  r3.y += d.y;  r3.z += d.z;  r3.w += d.w;
    }
    for (; sp < s; ++sp) {
        float4 a = ss[(size_t)sp * (DD / 4)];
        r0.x += a.x; r0.y += a.y; r0.z += a.z; r0.w += a.w;
    }
    float4 run;
    run.x = (r0.x + r1.x) + (r2.x + r3.x);
    run.y = (r0.y + r1.y) + (r2.y + r3.y);
    run.z = (r0.z + r1.z) + (r2.z + r3.z);
    run.w = (r0.w + r1.w) + (r2.w + r3.w);

    // add earlier quarters within this segment (qs still valid in smem)
#pragma unroll
    for (int qp = 0; qp < 3; ++qp) {
        if (qp < q) {
            float4 a = qs[qp][d4];
            run.x += a.x; run.y += a.y; run.z += a.z; run.w += a.w;
        }
    }

    float4* cp = reinterpret_cast<float4*>(g_cm) +
                 (size_t)(b * TT + tbase) * (DD / 4) + d4;
#pragma unroll
    for (int i = 0; i < QLEN; ++i) {
        float4 v = (i == 0) ? v0 : (i == 1) ? v1 : (i == 2) ? v2 : v3;
        run.x += v.x; run.y += v.y; run.z += v.z; run.w += v.w;
        float inv = 1.0f / (float)(tbase + i + 1);
        float4 o;
        o.x = run.x * inv; o.y = run.y * inv; o.z = run.z * inv; o.w = run.w * inv;
        cp[(size_t)i * (DD / 4)] = o;
    }
}

// ---------------------------------------------------------------------------
// Kernel 2: GEMM with cooperative cp.async pipeline (R5 shape: one
// __syncthreads per chunk keeps warps convoyed for DRAM locality).
// grid = T/2 = 512 blocks, 128 threads. 5 stages x 8 KB + 8 KB cm = 48 KB.
// ---------------------------------------------------------------------------
__device__ __forceinline__ void fma4(float4& acc, float s, const float4& v) {
    acc.x = fmaf(s, v.x, acc.x);
    acc.y = fmaf(s, v.y, acc.y);
    acc.z = fmaf(s, v.z, acc.z);
    acc.w = fmaf(s, v.w, acc.w);
}

__device__ __forceinline__ void cp16(void* smem_dst, const void* gmem_src) {
    uint32_t s = (uint32_t)__cvta_generic_to_shared(smem_dst);
    asm volatile("cp.async.cg.shared.global [%0], [%1], 16;\n"
                 :: "r"(s), "l"(gmem_src));
}

__global__ __launch_bounds__(128) void k_gemm(const float* __restrict__ W,
                                              float* __restrict__ out) {
    __shared__ float4 ws[STAGES][2][DCHUNK][OO / 4];  // 40 KB
    __shared__ float4 cm_s[2][BB][DD / 4];            // 8 KB

    int tid = threadIdx.x;
    int t0 = blockIdx.x * 2;
    int tg = tid >> 6;        // 0..1
    int o4 = tid & 63;        // float4 O-column

    const float4* W4 = reinterpret_cast<const float4*>(W);

    auto issue = [&](int st, int ch) {
#pragma unroll
        for (int k = 0; k < 4; ++k) {
            int slot = tid + k * 128;          // 0..511
            int tg_ = slot >> 8;
            int dd  = (slot >> 6) & (DCHUNK - 1);
            int oo  = slot & 63;
            const float4* src = W4 + ((size_t)(t0 + tg_) * DD +
                                      (ch * DCHUNK + dd)) * (OO / 4) + oo;
            cp16(&ws[st][tg_][dd][oo], src);
        }
    };

#pragma unroll
    for (int p = 0; p < STAGES - 1; ++p) {
        issue(p, p);
        asm volatile("cp.async.commit_group;\n" ::: "memory");
    }

    const float4* cm_g = reinterpret_cast<const float4*>(g_cm);
#pragma unroll
    for (int k = 0; k < 4; ++k) {
        int idx = tid + k * 128;
        int tg_ = idx >> 8;
        int b   = (idx >> 6) & 3;
        int d4_ = idx & 63;
        cm_s[tg_][b][d4_] = cm_g[(size_t)(b * TT + t0 + tg_) * (DD / 4) + d4_];
    }

    float4 a0 = make_float4(0.f, 0.f, 0.f, 0.f);
    float4 a1 = a0, a2 = a0, a3 = a0;

    int st = 0;
    for (int ch = 0; ch < NCHUNK; ++ch) {
        asm volatile("cp.async.wait_group %0;\n" :: "n"(STAGES - 2) : "memory");
        __syncthreads();

        float4 c0 = cm_s[tg][0][ch];
        float4 c1 = cm_s[tg][1][ch];
        float4 c2 = cm_s[tg][2][ch];
        float4 c3 = cm_s[tg][3][ch];

        {
            float4 w = ws[st][tg][0][o4];
            fma4(a0, c0.x, w); fma4(a1, c1.x, w); fma4(a2, c2.x, w); fma4(a3, c3.x, w);
        }
        {
            float4 w = ws[st][tg][1][o4];
            fma4(a0, c0.y, w); fma4(a1, c1.y, w); fma4(a2, c2.y, w); fma4(a3, c3.y, w);
        }
        {
            float4 w = ws[st][tg][2][o4];
            fma4(a0, c0.z, w); fma4(a1, c1.z, w); fma4(a2, c2.z, w); fma4(a3, c3.z, w);
        }
        {
            float4 w = ws[st][tg][3][o4];
            fma4(a0, c0.w, w); fma4(a1, c1.w, w); fma4(a2, c2.w, w); fma4(a3, c3.w, w);
        }

        // stage to refill = (st + STAGES-1) % STAGES (consumed one chunk ago)
        int stn = st + STAGES - 1;
        if (stn >= STAGES) stn -= STAGES;
        int nxt = ch + STAGES - 1;
        if (nxt < NCHUNK)
            issue(stn, nxt);
        asm volatile("cp.async.commit_group;\n" ::: "memory");

        if (++st == STAGES) st = 0;
    }

    int t = t0 + tg;
    float4* op = reinterpret_cast<float4*>(out);
    op[(size_t)(0 * TT + t) * (OO / 4) + o4] = a0;
    op[(size_t)(1 * TT + t) * (OO / 4) + o4] = a1;
    op[(size_t)(2 * TT + t) * (OO / 4) + o4] = a2;
    op[(size_t)(3 * TT + t) * (OO / 4) + o4] = a3;
}

extern "C" void kernel_launch(void* const* d_in, const int* in_sizes, int n_in,
                              void* d_out, int out_size) {
    const float* x = (const float*)d_in[0];   // (B,T,D)
    const float* W = (const float*)d_in[1];   // (T,D,O)
    float* out = (float*)d_out;               // (B,T,O)

    k_reset<<<1, BB * NSEG>>>();
    k_scan<<<BB * NSEG, 256>>>(x);
    k_gemm<<<TT / 2, 128>>>(W, out);
}

// round 9
// speedup vs baseline: 1.0670x; 1.0260x over previous
#include <cuda_runtime.h>
#include <cuda_bf16.h>
#include <cstdint>

// out[b,t,o] = (cummean_t x)[b,t,:] . W[t,:,o]
// B=4, T=1024, D=256, O=256. All fp32.

#define BB 4
#define TT 1024
#define DD 256
#define OO 256

#define NSEG 64
#define SEGLEN 16     // NSEG*SEGLEN == TT
#define QLEN 4        // 4 quarters x 4 rows per segment

#define STAGES 5
#define DCHUNK 4                 // d-rows per stage
#define NCHUNK (DD / DCHUNK)     // 64

__device__ float g_segsum[BB * NSEG * DD];      // 256 KB (L2-resident)
__device__ float g_cm[BB * TT * DD];            // 4 MB cumulative mean
__device__ unsigned g_ready[BB * NSEG];         // publish flags (zero-init; re-zeroed by k_gemm)

// ---------------------------------------------------------------------------
// Kernel 1: fused scan. grid = B*NSEG = 256 blocks (all co-resident),
// 256 threads = (q = tid>>6) x (d4 = tid&63).
// Phase 1: segment sum -> g_segsum, publish flag.
// Phase 2: poll prior segments' flags, prefix, write cumulative mean.
// ---------------------------------------------------------------------------
__device__ __forceinline__ unsigned ld_acquire(const unsigned* p) {
    unsigned v;
    asm volatile("ld.acquire.gpu.u32 %0, [%1];" : "=r"(v) : "l"(p));
    return v;
}

__global__ __launch_bounds__(256) void k_scan(const float* __restrict__ x) {
    __shared__ float4 qs[4][64];

    int b = blockIdx.x / NSEG;
    int s = blockIdx.x % NSEG;
    int d4 = threadIdx.x & 63;
    int q  = threadIdx.x >> 6;

    int tbase = s * SEGLEN + q * QLEN;
    const float4* xp = reinterpret_cast<const float4*>(x) +
                       (size_t)(b * TT + tbase) * (DD / 4) + d4;

    float4 v0 = xp[0 * (DD / 4)];
    float4 v1 = xp[1 * (DD / 4)];
    float4 v2 = xp[2 * (DD / 4)];
    float4 v3 = xp[3 * (DD / 4)];

    float4 qsum;
    qsum.x = (v0.x + v1.x) + (v2.x + v3.x);
    qsum.y = (v0.y + v1.y) + (v2.y + v3.y);
    qsum.z = (v0.z + v1.z) + (v2.z + v3.z);
    qsum.w = (v0.w + v1.w) + (v2.w + v3.w);
    qs[q][d4] = qsum;
    __syncthreads();

    // phase 1: q==0 threads write the segment sum, fence, then publish
    if (q == 0) {
        float4 a = qs[0][d4], b1 = qs[1][d4], c = qs[2][d4], d = qs[3][d4];
        float4 r;
        r.x = (a.x + b1.x) + (c.x + d.x);
        r.y = (a.y + b1.y) + (c.y + d.y);
        r.z = (a.z + b1.z) + (c.z + d.z);
        r.w = (a.w + b1.w) + (c.w + d.w);
        reinterpret_cast<float4*>(g_segsum)[(size_t)(b * NSEG + s) * (DD / 4) + d4] = r;
        __threadfence();
    }
    __syncthreads();
    if (threadIdx.x == 0)
        atomicExch(&g_ready[b * NSEG + s], 1u);

    // phase 2: wait for all prior segments of this b (parallel polling)
    if ((int)threadIdx.x < s) {
        const unsigned* flag = &g_ready[b * NSEG + threadIdx.x];
        while (ld_acquire(flag) == 0u) { }
    }
    __syncthreads();

    // prefix over prior segment sums (L2-resident, ILP-4)
    const float4* ss = reinterpret_cast<const float4*>(g_segsum) +
                       (size_t)b * NSEG * (DD / 4) + d4;
    float4 r0 = make_float4(0.f, 0.f, 0.f, 0.f);
    float4 r1 = r0, r2 = r0, r3 = r0;
    int sp = 0;
    for (; sp + 4 <= s; sp += 4) {
        float4 a = ss[(size_t)(sp + 0) * (DD / 4)];
        float4 bb = ss[(size_t)(sp + 1) * (DD / 4)];
        float4 c = ss[(size_t)(sp + 2) * (DD / 4)];
        float4 d = ss[(size_t)(sp + 3) * (DD / 4)];
        r0.x += a.x;  r0.y += a.y;  r0.z += a.z;  r0.w += a.w;
        r1.x += bb.x; r1.y += bb.y; r1.z += bb.z; r1.w += bb.w;
        r2.x += c.x;  r2.y += c.y;  r2.z += c.z;  r2.w += c.w;
        r3.x += d.x;  r3.y += d.y;  r3.z += d.z;  r3.w += d.w;
    }
    for (; sp < s; ++sp) {
        float4 a = ss[(size_t)sp * (DD / 4)];
        r0.x += a.x; r0.y += a.y; r0.z += a.z; r0.w += a.w;
    }
    float4 run;
    run.x = (r0.x + r1.x) + (r2.x + r3.x);
    run.y = (r0.y + r1.y) + (r2.y + r3.y);
    run.z = (r0.z + r1.z) + (r2.z + r3.z);
    run.w = (r0.w + r1.w) + (r2.w + r3.w);

    // add earlier quarters within this segment (qs still valid in smem)
#pragma unroll
    for (int qp = 0; qp < 3; ++qp) {
        if (qp < q) {
            float4 a = qs[qp][d4];
            run.x += a.x; run.y += a.y; run.z += a.z; run.w += a.w;
        }
    }

    float4* cp = reinterpret_cast<float4*>(g_cm) +
                 (size_t)(b * TT + tbase) * (DD / 4) + d4;
#pragma unroll
    for (int i = 0; i < QLEN; ++i) {
        float4 v = (i == 0) ? v0 : (i == 1) ? v1 : (i == 2) ? v2 : v3;
        run.x += v.x; run.y += v.y; run.z += v.z; run.w += v.w;
        float inv = 1.0f / (float)(tbase + i + 1);
        float4 o;
        o.x = run.x * inv; o.y = run.y * inv; o.z = run.z * inv; o.w = run.w * inv;
        cp[(size_t)i * (DD / 4)] = o;
    }
}

// ---------------------------------------------------------------------------
// Kernel 2: GEMM with cooperative cp.async pipeline (one __syncthreads per
// chunk keeps warps convoyed for DRAM locality). grid = T/2 = 512 blocks,
// 128 threads. 5 stages x 8 KB + 8 KB cm = 48 KB smem.
// Block 0 also re-zeroes g_ready for the next graph replay (runs after
// k_scan in-stream; statics are zero-init for the very first call).
// ---------------------------------------------------------------------------
__device__ __forceinline__ void fma4(float4& acc, float s, const float4& v) {
    acc.x = fmaf(s, v.x, acc.x);
    acc.y = fmaf(s, v.y, acc.y);
    acc.z = fmaf(s, v.z, acc.z);
    acc.w = fmaf(s, v.w, acc.w);
}

__device__ __forceinline__ void cp16(void* smem_dst, const void* gmem_src) {
    uint32_t s = (uint32_t)__cvta_generic_to_shared(smem_dst);
    asm volatile("cp.async.cg.shared.global [%0], [%1], 16;\n"
                 :: "r"(s), "l"(gmem_src));
}

__global__ __launch_bounds__(128) void k_gemm(const float* __restrict__ W,
                                              float* __restrict__ out) {
    __shared__ float4 ws[STAGES][2][DCHUNK][OO / 4];  // 40 KB
    __shared__ float4 cm_s[2][BB][DD / 4];            // 8 KB

    int tid = threadIdx.x;
    int t0 = blockIdx.x * 2;
    int tg = tid >> 6;        // 0..1
    int o4 = tid & 63;        // float4 O-column

    // flag reset for next replay (block 0 only; 2 words per thread)
    if (blockIdx.x == 0) {
        g_ready[tid] = 0u;
        g_ready[tid + 128] = 0u;
    }

    const float4* W4 = reinterpret_cast<const float4*>(W);

    auto issue = [&](int st, int ch) {
#pragma unroll
        for (int k = 0; k < 4; ++k) {
            int slot = tid + k * 128;          // 0..511
            int tg_ = slot >> 8;
            int dd  = (slot >> 6) & (DCHUNK - 1);
            int oo  = slot & 63;
            const float4* src = W4 + ((size_t)(t0 + tg_) * DD +
                                      (ch * DCHUNK + dd)) * (OO / 4) + oo;
            cp16(&ws[st][tg_][dd][oo], src);
        }
    };

#pragma unroll
    for (int p = 0; p < STAGES - 1; ++p) {
        issue(p, p);
        asm volatile("cp.async.commit_group;\n" ::: "memory");
    }

    const float4* cm_g = reinterpret_cast<const float4*>(g_cm);
#pragma unroll
    for (int k = 0; k < 4; ++k) {
        int idx = tid + k * 128;
        int tg_ = idx >> 8;
        int b   = (idx >> 6) & 3;
        int d4_ = idx & 63;
        cm_s[tg_][b][d4_] = cm_g[(size_t)(b * TT + t0 + tg_) * (DD / 4) + d4_];
    }

    float4 a0 = make_float4(0.f, 0.f, 0.f, 0.f);
    float4 a1 = a0, a2 = a0, a3 = a0;

    int st = 0;
    for (int ch = 0; ch < NCHUNK; ++ch) {
        asm volatile("cp.async.wait_group %0;\n" :: "n"(STAGES - 2) : "memory");
        __syncthreads();

        float4 c0 = cm_s[tg][0][ch];
        float4 c1 = cm_s[tg][1][ch];
        float4 c2 = cm_s[tg][2][ch];
        float4 c3 = cm_s[tg][3][ch];

        {
            float4 w = ws[st][tg][0][o4];
            fma4(a0, c0.x, w); fma4(a1, c1.x, w); fma4(a2, c2.x, w); fma4(a3, c3.x, w);
        }
        {
            float4 w = ws[st][tg][1][o4];
            fma4(a0, c0.y, w); fma4(a1, c1.y, w); fma4(a2, c2.y, w); fma4(a3, c3.y, w);
        }
        {
            float4 w = ws[st][tg][2][o4];
            fma4(a0, c0.z, w); fma4(a1, c1.z, w); fma4(a2, c2.z, w); fma4(a3, c3.z, w);
        }
        {
            float4 w = ws[st][tg][3][o4];
            fma4(a0, c0.w, w); fma4(a1, c1.w, w); fma4(a2, c2.w, w); fma4(a3, c3.w, w);
        }

        int stn = st + STAGES - 1;
        if (stn >= STAGES) stn -= STAGES;
        int nxt = ch + STAGES - 1;
        if (nxt < NCHUNK)
            issue(stn, nxt);
        asm volatile("cp.async.commit_group;\n" ::: "memory");

        if (++st == STAGES) st = 0;
    }

    int t = t0 + tg;
    float4* op = reinterpret_cast<float4*>(out);
    __stcs(&op[(size_t)(0 * TT + t) * (OO / 4) + o4], a0);
    __stcs(&op[(size_t)(1 * TT + t) * (OO / 4) + o4], a1);
    __stcs(&op[(size_t)(2 * TT + t) * (OO / 4) + o4], a2);
    __stcs(&op[(size_t)(3 * TT + t) * (OO / 4) + o4], a3);
}

extern "C" void kernel_launch(void* const* d_in, const int* in_sizes, int n_in,
                              void* d_out, int out_size) {
    const float* x = (const float*)d_in[0];   // (B,T,D)
    const float* W = (const float*)d_in[1];   // (T,D,O)
    float* out = (float*)d_out;               // (B,T,O)

    k_scan<<<BB * NSEG, 256>>>(x);
    k_gemm<<<TT / 2, 128>>>(W, out);
}

// round 10
// speedup vs baseline: 1.0701x; 1.0029x over previous
#include <cuda_runtime.h>
#include <cuda_bf16.h>
#include <cstdint>

// out[b,t,o] = (cummean_t x)[b,t,:] . W[t,:,o]
// B=4, T=1024, D=256, O=256. All fp32.
// Single fused kernel: 512 blocks x 128 threads, all co-resident (4 blocks/SM
// at 48KB smem). Blocks 0..255 compute the cumulative mean (one 16-long
// segment each) while every block's W cp.async prologue streams; grid-wide
// spin barriers order scan -> cm reads. Then the DRAM-bound GEMM mainloop.

#define BB 4
#define TT 1024
#define DD 256
#define OO 256

#define NSEG 64
#define SEGLEN 16

#define STAGES 5
#define DCHUNK 4                 // d-rows per stage
#define NCHUNK (DD / DCHUNK)     // 64

#define NBLK (TT / 2)            // 512
#define NSCAN (BB * NSEG)        // 256

__device__ float g_segsum[BB * NSEG * DD];      // 256 KB (L2-resident)
__device__ float g_cm[BB * TT * DD];            // 4 MB cumulative mean
__device__ unsigned g_bar_arr[2];               // zero-init; self-resetting
__device__ unsigned g_bar_dep[2];

__device__ __forceinline__ unsigned ld_acq(const unsigned* p) {
    unsigned v;
    asm volatile("ld.acquire.gpu.u32 %0, [%1];" : "=r"(v) : "l"(p));
    return v;
}

// grid barrier over n blocks; leader-only polling; self-resets for replay.
__device__ __forceinline__ void gbar(int i, unsigned n) {
    __syncthreads();
    if (threadIdx.x == 0) {
        __threadfence();
        atomicAdd(&g_bar_arr[i], 1u);
        while (ld_acq(&g_bar_arr[i]) < n) { __nanosleep(64); }
        unsigned d = atomicAdd(&g_bar_dep[i], 1u);
        if (d == n - 1u) {            // last departer: reset for next replay
            g_bar_arr[i] = 0u;
            __threadfence();
            g_bar_dep[i] = 0u;
        }
    }
    __syncthreads();
}

__device__ __forceinline__ void fma4(float4& acc, float s, const float4& v) {
    acc.x = fmaf(s, v.x, acc.x);
    acc.y = fmaf(s, v.y, acc.y);
    acc.z = fmaf(s, v.z, acc.z);
    acc.w = fmaf(s, v.w, acc.w);
}

__device__ __forceinline__ void add4(float4& a, const float4& v) {
    a.x += v.x; a.y += v.y; a.z += v.z; a.w += v.w;
}

__device__ __forceinline__ void cp16(void* smem_dst, const void* gmem_src) {
    uint32_t s = (uint32_t)__cvta_generic_to_shared(smem_dst);
    asm volatile("cp.async.cg.shared.global [%0], [%1], 16;\n"
                 :: "r"(s), "l"(gmem_src));
}

__global__ __launch_bounds__(128) void k_fused(const float* __restrict__ x,
                                               const float* __restrict__ W,
                                               float* __restrict__ out) {
    __shared__ float4 ws[STAGES][2][DCHUNK][OO / 4];  // 40 KB
    __shared__ float4 cm_s[2][BB][DD / 4];            // 8 KB (aliased by scan)

    int tid = threadIdx.x;
    int t0 = blockIdx.x * 2;
    int tg = tid >> 6;        // 0..1
    int o4 = tid & 63;        // float4 O-column

    const float4* W4 = reinterpret_cast<const float4*>(W);

    auto issue = [&](int st, int ch) {
#pragma unroll
        for (int k = 0; k < 4; ++k) {
            int slot = tid + k * 128;          // 0..511
            int tg_ = slot >> 8;
            int dd  = (slot >> 6) & (DCHUNK - 1);
            int oo  = slot & 63;
            const float4* src = W4 + ((size_t)(t0 + tg_) * DD +
                                      (ch * DCHUNK + dd)) * (OO / 4) + oo;
            cp16(&ws[st][tg_][dd][oo], src);
        }
    };

    // ---- W prefetch prologue: independent of cm, starts streaming now ----
#pragma unroll
    for (int p = 0; p < STAGES - 1; ++p) {
        issue(p, p);
        asm volatile("cp.async.commit_group;\n" ::: "memory");
    }

    // ---- scan phase (blocks 0..255): one (b, s) segment each ----
    bool is_scan = (blockIdx.x < NSCAN);
    if (is_scan) {
        // scratch aliases cm_s (cm_s is only loaded after gbar(1))
        float4 (*qs)[64] = reinterpret_cast<float4(*)[64]>(&cm_s[0][0][0]);

        int b = blockIdx.x >> 6;        // 0..3
        int s = blockIdx.x & 63;        // 0..63
        int d4 = tid & 63;
        int q  = tid >> 6;              // 0..1 (half-segment of 8 rows)
        int tbase = s * SEGLEN + q * 8;

        const float4* xp = reinterpret_cast<const float4*>(x) +
                           (size_t)(b * TT + tbase) * (DD / 4) + d4;
        float4 v[8];
        float4 hacc = make_float4(0.f, 0.f, 0.f, 0.f);
#pragma unroll
        for (int i = 0; i < 8; ++i) {
            v[i] = xp[(size_t)i * (DD / 4)];
            add4(hacc, v[i]);
        }
        qs[q][d4] = hacc;
        __syncthreads();

        if (q == 0) {
            float4 r = qs[0][d4];
            add4(r, qs[1][d4]);
            reinterpret_cast<float4*>(g_segsum)
                [(size_t)(b * NSEG + s) * (DD / 4) + d4] = r;
        }

        gbar(0, NSCAN);   // all segment sums visible

        // prefix over prior segments (L2-resident, ILP-4)
        const float4* ss = reinterpret_cast<const float4*>(g_segsum) +
                           (size_t)b * NSEG * (DD / 4) + d4;
        float4 r0 = make_float4(0.f, 0.f, 0.f, 0.f);
        float4 r1 = r0, r2 = r0, r3 = r0;
        int sp = 0;
        for (; sp + 4 <= s; sp += 4) {
            float4 a = ss[(size_t)(sp + 0) * (DD / 4)];
            float4 bb = ss[(size_t)(sp + 1) * (DD / 4)];
            float4 c = ss[(size_t)(sp + 2) * (DD / 4)];
            float4 d = ss[(size_t)(sp + 3) * (DD / 4)];
            add4(r0, a); add4(r1, bb); add4(r2, c); add4(r3, d);
        }
        for (; sp < s; ++sp)
            add4(r0, ss[(size_t)sp * (DD / 4)]);
        add4(r0, r1); add4(r2, r3); add4(r0, r2);
        float4 run = r0;
        if (q == 1)
            add4(run, qs[0][d4]);   // first half of this segment

        float4* cp = reinterpret_cast<float4*>(g_cm) +
                     (size_t)(b * TT + tbase) * (DD / 4) + d4;
#pragma unroll
        for (int i = 0; i < 8; ++i) {
            add4(run, v[i]);
            float inv = 1.0f / (float)(tbase + i + 1);
            float4 o;
            o.x = run.x * inv; o.y = run.y * inv;
            o.z = run.z * inv; o.w = run.w * inv;
            cp[(size_t)i * (DD / 4)] = o;
        }
    }

    gbar(1, NBLK);   // cm complete & visible to every block

    // ---- load cm tile ----
    const float4* cm_g = reinterpret_cast<const float4*>(g_cm);
#pragma unroll
    for (int k = 0; k < 4; ++k) {
        int idx = tid + k * 128;
        int tg_ = idx >> 8;
        int b   = (idx >> 6) & 3;
        int d4_ = idx & 63;
        cm_s[tg_][b][d4_] = cm_g[(size_t)(b * TT + t0 + tg_) * (DD / 4) + d4_];
    }

    // ---- GEMM mainloop (unchanged; 80% DRAM) ----
    float4 a0 = make_float4(0.f, 0.f, 0.f, 0.f);
    float4 a1 = a0, a2 = a0, a3 = a0;

    int st = 0;
    for (int ch = 0; ch < NCHUNK; ++ch) {
        asm volatile("cp.async.wait_group %0;\n" :: "n"(STAGES - 2) : "memory");
        __syncthreads();

        float4 c0 = cm_s[tg][0][ch];
        float4 c1 = cm_s[tg][1][ch];
        float4 c2 = cm_s[tg][2][ch];
        float4 c3 = cm_s[tg][3][ch];

        {
            float4 w = ws[st][tg][0][o4];
            fma4(a0, c0.x, w); fma4(a1, c1.x, w); fma4(a2, c2.x, w); fma4(a3, c3.x, w);
        }
        {
            float4 w = ws[st][tg][1][o4];
            fma4(a0, c0.y, w); fma4(a1, c1.y, w); fma4(a2, c2.y, w); fma4(a3, c3.y, w);
        }
        {
            float4 w = ws[st][tg][2][o4];
            fma4(a0, c0.z, w); fma4(a1, c1.z, w); fma4(a2, c2.z, w); fma4(a3, c3.z, w);
        }
        {
            float4 w = ws[st][tg][3][o4];
            fma4(a0, c0.w, w); fma4(a1, c1.w, w); fma4(a2, c2.w, w); fma4(a3, c3.w, w);
        }

        int stn = st + STAGES - 1;
        if (stn >= STAGES) stn -= STAGES;
        int nxt = ch + STAGES - 1;
        if (nxt < NCHUNK)
            issue(stn, nxt);
        asm volatile("cp.async.commit_group;\n" ::: "memory");

        if (++st == STAGES) st = 0;
    }

    int t = t0 + tg;
    float4* op = reinterpret_cast<float4*>(out);
    __stcs(&op[(size_t)(0 * TT + t) * (OO / 4) + o4], a0);
    __stcs(&op[(size_t)(1 * TT + t) * (OO / 4) + o4], a1);
    __stcs(&op[(size_t)(2 * TT + t) * (OO / 4) + o4], a2);
    __stcs(&op[(size_t)(3 * TT + t) * (OO / 4) + o4], a3);
}

extern "C" void kernel_launch(void* const* d_in, const int* in_sizes, int n_in,
                              void* d_out, int out_size) {
    const float* x = (const float*)d_in[0];   // (B,T,D)
    const float* W = (const float*)d_in[1];   // (T,D,O)
    float* out = (float*)d_out;               // (B,T,O)

    k_fused<<<NBLK, 128>>>(x, W, out);
}

// round 12
// speedup vs baseline: 1.0948x; 1.0231x over previous
#include <cuda_runtime.h>
#include <cuda_bf16.h>
#include <cstdint>

// out[b,t,o] = (cummean_t x)[b,t,:] . W[t,:,o]
// B=4, T=1024, D=256, O=256. All fp32.
// Single fused kernel: 512 blocks x 128 threads, all co-resident (4/SM at
// 48KB smem). ALL blocks scan one 8-long segment (4b x 128s = 512), with W
// cp.async prologue + L2 prefetch of upcoming W chunks filling the DRAM idle
// window around the grid barriers. Then the DRAM-bound GEMM mainloop.

#define BB 4
#define TT 1024
#define DD 256
#define OO 256

#define NSEG 128
#define SEGLEN 8

#define STAGES 5
#define DCHUNK 4                 // d-rows per stage
#define NCHUNK (DD / DCHUNK)     // 64

#define NBLK (TT / 2)            // 512 == BB * NSEG

__device__ float g_segsum[BB * NSEG * DD];      // 512 KB (L2-resident)
__device__ float g_cm[BB * TT * DD];            // 4 MB cumulative mean
__device__ unsigned g_bar_arr[2];               // zero-init; self-resetting
__device__ unsigned g_bar_dep[2];

__device__ __forceinline__ unsigned ld_acq(const unsigned* p) {
    unsigned v;
    asm volatile("ld.acquire.gpu.u32 %0, [%1];" : "=r"(v) : "l"(p));
    return v;
}

// grid barrier over n blocks; leader-only polling; self-resets for replay.
__device__ __forceinline__ void gbar(int i, unsigned n) {
    __syncthreads();
    if (threadIdx.x == 0) {
        __threadfence();
        atomicAdd(&g_bar_arr[i], 1u);
        while (ld_acq(&g_bar_arr[i]) < n) { __nanosleep(64); }
        unsigned d = atomicAdd(&g_bar_dep[i], 1u);
        if (d == n - 1u) {            // last departer: reset for next replay
            g_bar_arr[i] = 0u;
            __threadfence();
            g_bar_dep[i] = 0u;
        }
    }
    __syncthreads();
}

__device__ __forceinline__ void fma4(float4& acc, float s, const float4& v) {
    acc.x = fmaf(s, v.x, acc.x);
    acc.y = fmaf(s, v.y, acc.y);
    acc.z = fmaf(s, v.z, acc.z);
    acc.w = fmaf(s, v.w, acc.w);
}

__device__ __forceinline__ void add4(float4& a, const float4& v) {
    a.x += v.x; a.y += v.y; a.z += v.z; a.w += v.w;
}

__device__ __forceinline__ void cp16(void* smem_dst, const void* gmem_src) {
    uint32_t s = (uint32_t)__cvta_generic_to_shared(smem_dst);
    asm volatile("cp.async.cg.shared.global [%0], [%1], 16;\n"
                 :: "r"(s), "l"(gmem_src));
}

__device__ __forceinline__ void pfl2(const void* p) {
    asm volatile("prefetch.global.L2 [%0];" :: "l"(p));
}

__global__ __launch_bounds__(128) void k_fused(const float* __restrict__ x,
                                               const float* __restrict__ W,
                                               float* __restrict__ out) {
    __shared__ float4 ws[STAGES][2][DCHUNK][OO / 4];  // 40 KB
    __shared__ float4 cm_s[2][BB][DD / 4];            // 8 KB (aliased by scan)

    int tid = threadIdx.x;
    int t0 = blockIdx.x * 2;
    int tg = tid >> 6;        // 0..1
    int o4 = tid & 63;        // float4 O-column

    const float4* W4 = reinterpret_cast<const float4*>(W);

    auto issue = [&](int st, int ch) {
#pragma unroll
        for (int k = 0; k < 4; ++k) {
            int slot = tid + k * 128;          // 0..511
            int tg_ = slot >> 8;
            int dd  = (slot >> 6) & (DCHUNK - 1);
            int oo  = slot & 63;
            const float4* src = W4 + ((size_t)(t0 + tg_) * DD +
                                      (ch * DCHUNK + dd)) * (OO / 4) + oo;
            cp16(&ws[st][tg_][dd][oo], src);
        }
    };

    // ---- W prefetch prologue: independent of cm, starts streaming now ----
#pragma unroll
    for (int p = 0; p < STAGES - 1; ++p) {
        issue(p, p);
        asm volatile("cp.async.commit_group;\n" ::: "memory");
    }

    // ---- scan phase: every block scans one (b, s) 8-row segment ----
    {
        // scratch aliases cm_s (cm_s is only loaded after gbar(1))
        float4 (*qs)[64] = reinterpret_cast<float4(*)[64]>(&cm_s[0][0][0]);

        int b = blockIdx.x >> 7;        // 0..3
        int s = blockIdx.x & 127;       // 0..127
        int d4 = tid & 63;
        int q  = tid >> 6;              // 0..1 (half-segment of 4 rows)
        int tbase = s * SEGLEN + q * 4;

        const float4* xp = reinterpret_cast<const float4*>(x) +
                           (size_t)(b * TT + tbase) * (DD / 4) + d4;
        float4 v[4];
        float4 hacc = make_float4(0.f, 0.f, 0.f, 0.f);
#pragma unroll
        for (int i = 0; i < 4; ++i) {
            v[i] = xp[(size_t)i * (DD / 4)];
            add4(hacc, v[i]);
        }
        qs[q][d4] = hacc;
        __syncthreads();

        if (q == 0) {
            float4 r = qs[0][d4];
            add4(r, qs[1][d4]);
            reinterpret_cast<float4*>(g_segsum)
                [(size_t)(b * NSEG + s) * (DD / 4) + d4] = r;
        }

        gbar(0, NBLK);   // all segment sums visible

        // prefix over prior segments (L2-resident, ILP-4)
        const float4* ss = reinterpret_cast<const float4*>(g_segsum) +
                           (size_t)b * NSEG * (DD / 4) + d4;
        float4 r0 = make_float4(0.f, 0.f, 0.f, 0.f);
        float4 r1 = r0, r2 = r0, r3 = r0;
        int sp = 0;
        for (; sp + 4 <= s; sp += 4) {
            float4 a = ss[(size_t)(sp + 0) * (DD / 4)];
            float4 bb = ss[(size_t)(sp + 1) * (DD / 4)];
            float4 c = ss[(size_t)(sp + 2) * (DD / 4)];
            float4 d = ss[(size_t)(sp + 3) * (DD / 4)];
            add4(r0, a); add4(r1, bb); add4(r2, c); add4(r3, d);
        }
        for (; sp < s; ++sp)
            add4(r0, ss[(size_t)sp * (DD / 4)]);
        add4(r0, r1); add4(r2, r3); add4(r0, r2);
        float4 run = r0;
        if (q == 1)
            add4(run, qs[0][d4]);   // first half of this segment

        float4* cp = reinterpret_cast<float4*>(g_cm) +
                     (size_t)(b * TT + tbase) * (DD / 4) + d4;
#pragma unroll
        for (int i = 0; i < 4; ++i) {
            add4(run, v[i]);
            float inv = 1.0f / (float)(tbase + i + 1);
            float4 o;
            o.x = run.x * inv; o.y = run.y * inv;
            o.z = run.z * inv; o.w = run.w * inv;
            cp[(size_t)i * (DD / 4)] = o;
        }
    }

    // ---- L2-prefetch upcoming W chunks (4..15) while waiting at barrier ----
    // per block: 2 t-rows x bytes [16KB, 64KB) of each 256KB row = 96 KB
    {
        const char* wrow0 = reinterpret_cast<const char*>(W) +
                            (size_t)t0 * DD * OO * 4;
#pragma unroll
        for (int tg_ = 0; tg_ < 2; ++tg_) {
            const char* base = wrow0 + (size_t)tg_ * DD * OO * 4;
#pragma unroll
            for (int it = 0; it < 3; ++it) {
                pfl2(base + 16384 + (size_t)it * 16384 + tid * 128);
            }
        }
    }

    gbar(1, NBLK);   // cm complete & visible to every block

    // ---- load cm tile ----
    const float4* cm_g = reinterpret_cast<const float4*>(g_cm);
#pragma unroll
    for (int k = 0; k < 4; ++k) {
        int idx = tid + k * 128;
        int tg_ = idx >> 8;
        int b   = (idx >> 6) & 3;
        int d4_ = idx & 63;
        cm_s[tg_][b][d4_] = cm_g[(size_t)(b * TT + t0 + tg_) * (DD / 4) + d4_];
    }

    // ---- GEMM mainloop (DRAM-bound streamer) ----
    float4 a0 = make_float4(0.f, 0.f, 0.f, 0.f);
    float4 a1 = a0, a2 = a0, a3 = a0;

    int st = 0;
    for (int ch = 0; ch < NCHUNK; ++ch) {
        asm volatile("cp.async.wait_group %0;\n" :: "n"(STAGES - 2) : "memory");
        __syncthreads();

        float4 c0 = cm_s[tg][0][ch];
        float4 c1 = cm_s[tg][1][ch];
        float4 c2 = cm_s[tg][2][ch];
        float4 c3 = cm_s[tg][3][ch];

        {
            float4 w = ws[st][tg][0][o4];
            fma4(a0, c0.x, w); fma4(a1, c1.x, w); fma4(a2, c2.x, w); fma4(a3, c3.x, w);
        }
        {
            float4 w = ws[st][tg][1][o4];
            fma4(a0, c0.y, w); fma4(a1, c1.y, w); fma4(a2, c2.y, w); fma4(a3, c3.y, w);
        }
        {
            float4 w = ws[st][tg][2][o4];
            fma4(a0, c0.z, w); fma4(a1, c1.z, w); fma4(a2, c2.z, w); fma4(a3, c3.z, w);
        }
        {
            float4 w = ws[st][tg][3][o4];
            fma4(a0, c0.w, w); fma4(a1, c1.w, w); fma4(a2, c2.w, w); fma4(a3, c3.w, w);
        }

        int stn = st + STAGES - 1;
        if (stn >= STAGES) stn -= STAGES;
        int nxt = ch + STAGES - 1;
        if (nxt < NCHUNK)
            issue(stn, nxt);
        asm volatile("cp.async.commit_group;\n" ::: "memory");

        if (++st == STAGES) st = 0;
    }

    int t = t0 + tg;
    float4* op = reinterpret_cast<float4*>(out);
    __stcs(&op[(size_t)(0 * TT + t) * (OO / 4) + o4], a0);
    __stcs(&op[(size_t)(1 * TT + t) * (OO / 4) + o4], a1);
    __stcs(&op[(size_t)(2 * TT + t) * (OO / 4) + o4], a2);
    __stcs(&op[(size_t)(3 * TT + t) * (OO / 4) + o4], a3);
}

extern "C" void kernel_launch(void* const* d_in, const int* in_sizes, int n_in,
                              void* d_out, int out_size) {
    const float* x = (const float*)d_in[0];   // (B,T,D)
    const float* W = (const float*)d_in[1];   // (T,D,O)
    float* out = (float*)d_out;               // (B,T,O)

    k_fused<<<NBLK, 128>>>(x, W, out);
}